// round 11
// baseline (speedup 1.0000x reference)
#include <cuda_runtime.h>
#include <cuda_bf16.h>
#include <cstdint>

#define NSRC  200000
#define NDST  100000
#define NEDGE 500000
#define DF    128
#define KTOT  256            // concat feature dim (agg | self)
#define SCAN_BLOCKS 98       // ceil(100000/1024)

// ---------------- static device scratch (no allocations allowed) ----------------
static __device__ __align__(16) __nv_bfloat16 g_Whi[DF * KTOT];  // [n=128][k=256]
static __device__ __align__(16) __nv_bfloat16 g_Wlo[DF * KTOT];
static __device__ int   g_counts[NDST];
static __device__ int   g_cursor[NDST];
static __device__ int   g_offsets[NDST];        // per-1024-block exclusive scan
static __device__ int   g_blocksums[SCAN_BLOCKS];
static __device__ int   g_sorted_src[NEDGE];

// ---------------- sort / CSR kernels ----------------
__global__ void zero_kernel() {
    int i = blockIdx.x * blockDim.x + threadIdx.x;
    if (i < NDST) { g_counts[i] = 0; g_cursor[i] = 0; }
}

__global__ void hist_kernel(const int* __restrict__ dst_idx) {
    int i = blockIdx.x * blockDim.x + threadIdx.x;
    if (i < NEDGE) atomicAdd(&g_counts[dst_idx[i]], 1);
}

// scan1 + W split build fused (98x1024 threads cover both)
__global__ void scan1_kernel(const float* __restrict__ W1,
                             const float* __restrict__ W2) {
    int t = threadIdx.x;
    int i = blockIdx.x * 1024 + t;

    // --- W split (first 32 blocks' worth of threads) ---
    if (i < DF * KTOT) {
        int n = i >> 8, k = i & 255;
        float v = (k < DF) ? W1[n * DF + k] : W2[n * DF + (k - DF)];
        __nv_bfloat16 h = __float2bfloat16_rn(v);
        g_Whi[i] = h;
        g_Wlo[i] = __float2bfloat16_rn(v - __bfloat162float(h));
    }

    // --- per-block exclusive scan of counts ---
    __shared__ int s[1024];
    int v = (i < NDST) ? g_counts[i] : 0;
    s[t] = v;
    __syncthreads();
    for (int off = 1; off < 1024; off <<= 1) {
        int add = (t >= off) ? s[t - off] : 0;
        __syncthreads();
        s[t] += add;
        __syncthreads();
    }
    if (i < NDST) g_offsets[i] = s[t] - v;      // exclusive within block
    if (t == 1023) g_blocksums[blockIdx.x] = s[1023];
}

__global__ void scan2_kernel() {
    __shared__ int s[SCAN_BLOCKS];
    int t = threadIdx.x;               // 128 threads
    if (t < SCAN_BLOCKS) s[t] = g_blocksums[t];
    __syncthreads();
    if (t == 0) {
        int run = 0;
        for (int b = 0; b < SCAN_BLOCKS; ++b) { int tv = s[b]; s[b] = run; run += tv; }
    }
    __syncthreads();
    if (t < SCAN_BLOCKS) g_blocksums[t] = s[t];
}

// scatter with on-the-fly global offset (scan3 folded in)
__global__ void scatter_kernel(const int* __restrict__ src_idx,
                               const int* __restrict__ dst_idx) {
    int i = blockIdx.x * blockDim.x + threadIdx.x;
    if (i < NEDGE) {
        int d = dst_idx[i];
        int pos = g_offsets[d] + g_blocksums[d >> 10] + atomicAdd(&g_cursor[d], 1);
        g_sorted_src[pos] = src_idx[i];
    }
}

// ---------------- fused agg + split-bf16 tensor-core GEMM ----------------------
// Per block: aggregate 128 dst rows (full K=256) into smem as split bf16,
// then C[128,128] = A[128,256] @ W^T with 3 mma passes (hi*hi + hi*lo + lo*hi).
#define MT    128            // rows per block
#define ASTR  264            // A smem stride (bf16): 528B -> ldmatrix conflict-free
#define KC    64             // W chunk
#define BSTR  72             // W smem stride (bf16): 144B -> conflict-free
#define FUSED_SMEM ((2 * MT * ASTR + 2 * MT * BSTR) * (int)sizeof(__nv_bfloat16))

__device__ __forceinline__ uint32_t smaddr(const void* p) {
    return (uint32_t)__cvta_generic_to_shared(p);
}
__device__ __forceinline__ void ldmx4(uint32_t& r0, uint32_t& r1, uint32_t& r2,
                                      uint32_t& r3, uint32_t a) {
    asm volatile("ldmatrix.sync.aligned.m8n8.x4.shared.b16 {%0,%1,%2,%3}, [%4];\n"
                 : "=r"(r0), "=r"(r1), "=r"(r2), "=r"(r3) : "r"(a));
}
__device__ __forceinline__ void mma16816(float* d, const uint32_t* a, const uint32_t* b) {
    asm volatile(
        "mma.sync.aligned.m16n8k16.row.col.f32.bf16.bf16.f32 "
        "{%0,%1,%2,%3}, {%4,%5,%6,%7}, {%8,%9}, {%0,%1,%2,%3};\n"
        : "+f"(d[0]), "+f"(d[1]), "+f"(d[2]), "+f"(d[3])
        : "r"(a[0]), "r"(a[1]), "r"(a[2]), "r"(a[3]), "r"(b[0]), "r"(b[1]));
}

__device__ __forceinline__ int csr_off(int r) {
    return g_offsets[r] + g_blocksums[r >> 10];
}

__device__ __forceinline__ void split_pack4(__nv_bfloat16* hi, __nv_bfloat16* lo,
                                            float4 a) {
    __nv_bfloat16 h0 = __float2bfloat16_rn(a.x);
    __nv_bfloat16 h1 = __float2bfloat16_rn(a.y);
    __nv_bfloat16 h2 = __float2bfloat16_rn(a.z);
    __nv_bfloat16 h3 = __float2bfloat16_rn(a.w);
    reinterpret_cast<__nv_bfloat162*>(hi)[0] = __nv_bfloat162(h0, h1);
    reinterpret_cast<__nv_bfloat162*>(hi)[1] = __nv_bfloat162(h2, h3);
    reinterpret_cast<__nv_bfloat162*>(lo)[0] =
        __nv_bfloat162(__float2bfloat16_rn(a.x - __bfloat162float(h0)),
                       __float2bfloat16_rn(a.y - __bfloat162float(h1)));
    reinterpret_cast<__nv_bfloat162*>(lo)[1] =
        __nv_bfloat162(__float2bfloat16_rn(a.z - __bfloat162float(h2)),
                       __float2bfloat16_rn(a.w - __bfloat162float(h3)));
}

__global__ __launch_bounds__(256, 1)
void fused_kernel(const float* __restrict__ x,
                  const float* __restrict__ degree,
                  const int*  __restrict__ self_ids,
                  float* __restrict__ out) {
    extern __shared__ __nv_bfloat16 sm[];
    __nv_bfloat16* Ah = sm;                          // [128][264] full K
    __nv_bfloat16* Al = Ah + MT * ASTR;
    __nv_bfloat16* Bh = Al + MT * ASTR;              // [128][72] per KC chunk
    __nv_bfloat16* Bl = Bh + MT * BSTR;

    int tid  = threadIdx.x;
    int lane = tid & 31;
    int w    = tid >> 5;          // 8 warps
    int m0   = blockIdx.x * MT;

    // ---------------- phase 1: aggregate + self-gather into smem --------------
    for (int rr = w; rr < MT; rr += 8) {
        int row = m0 + rr;
        __nv_bfloat16* ahp = &Ah[rr * ASTR + lane * 4];
        __nv_bfloat16* alp = &Al[rr * ASTR + lane * 4];
        if (row < NDST) {
            // self gather (independent, issue first)
            int sid = __ldg(&self_ids[row]);
            float4 sv = __ldg(reinterpret_cast<const float4*>(
                &x[(size_t)sid * DF + lane * 4]));

            int beg = csr_off(row);
            int end = (row == NDST - 1) ? NEDGE : csr_off(row + 1);
            float4 a0 = make_float4(0.f, 0.f, 0.f, 0.f);
            float4 a1 = make_float4(0.f, 0.f, 0.f, 0.f);
            float4 a2 = make_float4(0.f, 0.f, 0.f, 0.f);
            float4 a3 = make_float4(0.f, 0.f, 0.f, 0.f);
            int j = beg;
            for (; j + 3 < end; j += 4) {
                int s0 = __ldg(&g_sorted_src[j]);
                int s1 = __ldg(&g_sorted_src[j + 1]);
                int s2 = __ldg(&g_sorted_src[j + 2]);
                int s3 = __ldg(&g_sorted_src[j + 3]);
                float4 v0 = __ldg(reinterpret_cast<const float4*>(&x[(size_t)s0 * DF + lane * 4]));
                float4 v1 = __ldg(reinterpret_cast<const float4*>(&x[(size_t)s1 * DF + lane * 4]));
                float4 v2 = __ldg(reinterpret_cast<const float4*>(&x[(size_t)s2 * DF + lane * 4]));
                float4 v3 = __ldg(reinterpret_cast<const float4*>(&x[(size_t)s3 * DF + lane * 4]));
                a0.x += v0.x; a0.y += v0.y; a0.z += v0.z; a0.w += v0.w;
                a1.x += v1.x; a1.y += v1.y; a1.z += v1.z; a1.w += v1.w;
                a2.x += v2.x; a2.y += v2.y; a2.z += v2.z; a2.w += v2.w;
                a3.x += v3.x; a3.y += v3.y; a3.z += v3.z; a3.w += v3.w;
            }
            for (; j < end; ++j) {
                int s0 = __ldg(&g_sorted_src[j]);
                float4 v0 = __ldg(reinterpret_cast<const float4*>(&x[(size_t)s0 * DF + lane * 4]));
                a0.x += v0.x; a0.y += v0.y; a0.z += v0.z; a0.w += v0.w;
            }
            float inv = 1.0f / __ldg(&degree[row]);
            a0.x = (a0.x + a1.x + a2.x + a3.x) * inv;
            a0.y = (a0.y + a1.y + a2.y + a3.y) * inv;
            a0.z = (a0.z + a1.z + a2.z + a3.z) * inv;
            a0.w = (a0.w + a1.w + a2.w + a3.w) * inv;
            split_pack4(ahp, alp, a0);
            split_pack4(ahp + DF, alp + DF, sv);
        } else {
            float4 z = make_float4(0.f, 0.f, 0.f, 0.f);
            split_pack4(ahp, alp, z);
            split_pack4(ahp + DF, alp + DF, z);
        }
    }

    // ---------------- phase 2: MMA -------------------------------------------
    int wm = w >> 2, wn = w & 3;               // 2 (m) x 4 (n) warp grid
    float acc[4][4][4];
#pragma unroll
    for (int mi = 0; mi < 4; ++mi)
#pragma unroll
        for (int ni = 0; ni < 4; ++ni)
#pragma unroll
            for (int q = 0; q < 4; ++q) acc[mi][ni][q] = 0.f;

    int arow  = wm * 64 + (lane & 7) + ((lane >> 3) & 1) * 8;
    int acolo = ((lane >> 4) & 1) * 8;
    int brow  = wn * 32 + (lane & 7) + ((lane >> 4) & 1) * 8;
    int bcolo = ((lane >> 3) & 1) * 8;

    for (int kc = 0; kc < KTOT; kc += KC) {
        __syncthreads();   // A ready (first iter) / B safe to overwrite
#pragma unroll
        for (int it = 0; it < 4; ++it) {
            int lin = it * 256 + tid;          // 1024 16B-chunks per B tile
            int r = lin >> 3, c8 = (lin & 7) * 8;
            *reinterpret_cast<uint4*>(&Bh[r * BSTR + c8]) =
                *reinterpret_cast<const uint4*>(&g_Whi[r * KTOT + kc + c8]);
            *reinterpret_cast<uint4*>(&Bl[r * BSTR + c8]) =
                *reinterpret_cast<const uint4*>(&g_Wlo[r * KTOT + kc + c8]);
        }
        __syncthreads();

#pragma unroll
        for (int ks = 0; ks < KC; ks += 16) {
            uint32_t ah[4][4], al[4][4], bh[4][2], bl[4][2];
#pragma unroll
            for (int mi = 0; mi < 4; ++mi) {
                ldmx4(ah[mi][0], ah[mi][1], ah[mi][2], ah[mi][3],
                      smaddr(&Ah[(arow + mi * 16) * ASTR + kc + ks + acolo]));
                ldmx4(al[mi][0], al[mi][1], al[mi][2], al[mi][3],
                      smaddr(&Al[(arow + mi * 16) * ASTR + kc + ks + acolo]));
            }
#pragma unroll
            for (int np = 0; np < 2; ++np) {
                uint32_t r0, r1, r2, r3;
                ldmx4(r0, r1, r2, r3, smaddr(&Bh[(brow + np * 16) * BSTR + ks + bcolo]));
                bh[np * 2][0] = r0; bh[np * 2][1] = r1;
                bh[np * 2 + 1][0] = r2; bh[np * 2 + 1][1] = r3;
                ldmx4(r0, r1, r2, r3, smaddr(&Bl[(brow + np * 16) * BSTR + ks + bcolo]));
                bl[np * 2][0] = r0; bl[np * 2][1] = r1;
                bl[np * 2 + 1][0] = r2; bl[np * 2 + 1][1] = r3;
            }
#pragma unroll
            for (int mi = 0; mi < 4; ++mi)
#pragma unroll
                for (int ni = 0; ni < 4; ++ni) {
                    mma16816(acc[mi][ni], ah[mi], bh[ni]);   // hi*hi
                    mma16816(acc[mi][ni], ah[mi], bl[ni]);   // hi*lo
                    mma16816(acc[mi][ni], al[mi], bh[ni]);   // lo*hi
                }
        }
    }

    // epilogue
#pragma unroll
    for (int mi = 0; mi < 4; ++mi) {
#pragma unroll
        for (int ni = 0; ni < 4; ++ni) {
            int row = m0 + wm * 64 + mi * 16 + (lane >> 2);
            int col = wn * 32 + ni * 8 + 2 * (lane & 3);
            if (row < NDST) {
                float2 v = make_float2(acc[mi][ni][0], acc[mi][ni][1]);
                *reinterpret_cast<float2*>(&out[(size_t)row * DF + col]) = v;
            }
            if (row + 8 < NDST) {
                float2 v = make_float2(acc[mi][ni][2], acc[mi][ni][3]);
                *reinterpret_cast<float2*>(&out[(size_t)(row + 8) * DF + col]) = v;
            }
        }
    }
}

// ---------------- launch ----------------
extern "C" void kernel_launch(void* const* d_in, const int* in_sizes, int n_in,
                              void* d_out, int out_size) {
    const float* x       = (const float*)d_in[0];
    const float* W1      = (const float*)d_in[1];
    const float* W2      = (const float*)d_in[2];
    const float* degree  = (const float*)d_in[3];
    const int*   src_idx = (const int*)  d_in[4];
    const int*   dst_idx = (const int*)  d_in[5];
    const int*   self_ids= (const int*)  d_in[6];
    float* out = (float*)d_out;

    cudaFuncSetAttribute(fused_kernel,
                         cudaFuncAttributeMaxDynamicSharedMemorySize, FUSED_SMEM);

    zero_kernel   <<<(NDST + 255) / 256, 256>>>();                       // 0
    hist_kernel   <<<(NEDGE + 255) / 256, 256>>>(dst_idx);               // 1
    scan1_kernel  <<<SCAN_BLOCKS, 1024>>>(W1, W2);                       // 2
    scan2_kernel  <<<1, 128>>>();                                        // 3
    scatter_kernel<<<(NEDGE + 255) / 256, 256>>>(src_idx, dst_idx);      // 4
    fused_kernel  <<<(NDST + MT - 1) / MT, 256, FUSED_SMEM>>>(           // 5 <- ncu slot
        x, degree, self_ids, out);
}